// round 11
// baseline (speedup 1.0000x reference)
#include <cuda_runtime.h>
#include <cstdint>

// Problem constants (fixed shapes for this problem)
#define Bc 8
#define Hc 1024
#define Ec 512
#define Vc 32000
#define Tc 100
#define KVc 1536   // H + E   (x_v width)
#define KKc 2560   // 2H + E  (x_k width)

#define GRID_MAIN 592          // 4 blocks per SM on 148 SMs, single wave
// 16000 warp-jobs = 592*27 + 16 -> first 16 blocks take 28 jobs, rest 27
// job j: tile = j>>1 (4 vocab rows), batch group = j&1 (batches g*4..g*4+3)

// Scratch (device globals; zero-initialized at module load, no runtime alloc)
__device__ int   g_cnt[Bc * Vc];               // topic word counts (kept zero between runs)
__device__ float g_ekval[Bc * Vc];             // e_k values (valid only where cnt>0)
__device__ float g_psum[GRID_MAIN * Bc];       // per-BLOCK partial softmax sums

// ---------------------------------------------------------------------------
// Kernel 1: count topic words + compute e_k for each (b, topic word) pair.
// 4 warps per pair (each warp covers 640 of 2560 columns), smem combine.
// 800 pairs -> 400 blocks x 256 threads (2 pairs per block).   [proven R5]
// ---------------------------------------------------------------------------
__global__ void __launch_bounds__(256) count_ek_kernel(const int*   __restrict__ topics,
                                                       const float* __restrict__ outp,
                                                       const float* __restrict__ inp,
                                                       const float* __restrict__ ctx,
                                                       const float* __restrict__ WK,
                                                       const float* __restrict__ bK) {
    __shared__ float part[2][4];

    int tid  = threadIdx.x;
    int warp = tid >> 5;
    int lane = tid & 31;
    int lp   = warp >> 2;        // local pair 0/1
    int q    = warp & 3;         // quarter of the 2560-dot
    int pair = blockIdx.x * 2 + lp;

    int b   = pair / Tc;
    int idx = topics[pair];

    float s = 0.f;
    if (idx != 0) {
        const float* wrow = WK + (size_t)idx * KKc + q * 640;
        int cbase = q * 640 + lane * 4;
        #pragma unroll
        for (int i = 0; i < 5; i++) {
            int cc = cbase + i * 128;
            float4 wv = *(const float4*)(wrow + lane * 4 + i * 128);
            float4 xv;
            if (cc < Hc)            xv = *(const float4*)(outp + b * Hc + cc);
            else if (cc < Hc + Ec)  xv = *(const float4*)(inp  + b * Ec + (cc - Hc));
            else                    xv = *(const float4*)(ctx  + b * Hc + (cc - Hc - Ec));
            s += wv.x * xv.x + wv.y * xv.y + wv.z * xv.z + wv.w * xv.w;
        }
        #pragma unroll
        for (int h = 16; h >= 1; h >>= 1) s += __shfl_xor_sync(0xffffffffu, s, h);
    }
    if (lane == 0) part[lp][q] = s;
    __syncthreads();

    if (tid < 2) {
        int p2 = blockIdx.x * 2 + tid;
        int b2 = p2 / Tc;
        int i2 = topics[p2];
        if (i2 != 0) {
            float e = part[tid][0] + part[tid][1] + part[tid][2] + part[tid][3];
            atomicAdd(&g_cnt[b2 * Vc + i2], 1);
            g_ekval[b2 * Vc + i2] = e + bK[i2];   // duplicates write identical values
        }
    }
}

// ---------------------------------------------------------------------------
// Kernel 2: main GEMV + gate + tanh + exp + block-level partial sums.
// Batch-split tiles: each warp does 4 vocab rows x 4 batches (16 accs,
// ~55 regs) -> 4 blocks/SM, 32 warps/SM. Two warps per tile (one per batch
// group); W rows are re-read by the sibling warp (L1/L2-served).
// ---------------------------------------------------------------------------
__global__ void __launch_bounds__(256, 4) main_kernel(const float* __restrict__ outp,
                                                      const float* __restrict__ inp,
                                                      const float* __restrict__ WV,
                                                      const float* __restrict__ bV,
                                                      float* __restrict__ out) {
    __shared__ float xs[Bc * KVc];   // 49152 bytes (exactly 48 KB)
    __shared__ float sm_ps[8 * 4];   // per-warp sums (4 batches each)

    int tid  = threadIdx.x;
    int warp = tid >> 5;
    int lane = tid & 31;

    // cooperative fill of x_v = concat(output, input_step) per batch
    for (int i = tid; i < (Bc * KVc) / 4; i += 256) {
        int fi = i * 4;
        int b = fi / KVc;
        int c = fi % KVc;
        float4 v;
        if (c < Hc) v = *(const float4*)(outp + b * Hc + c);
        else        v = *(const float4*)(inp  + b * Ec + (c - Hc));
        *(float4*)(xs + fi) = v;
    }
    __syncthreads();

    int blk   = blockIdx.x;
    int jbase = blk * 27 + (blk < 16 ? blk : 16);
    int jcnt  = 27 + (blk < 16 ? 1 : 0);

    // batch group is constant per warp: consecutive jobs alternate groups,
    // warp stride is 8 (even), so group = (jbase + warp) & 1.
    int grp  = (jbase + warp) & 1;
    int gb0  = grp * 4;              // first batch of this warp's group

    float lsum = 0.f;                // per-lane partial (lane<16: batch gb0+(lane&3))

    #pragma unroll 1
    for (int k = warp; k < jcnt; k += 8) {
        int job  = jbase + k;
        int tile = job >> 1;
        int w0   = tile * 4;

        float acc[16];               // j = r*4 + bb  (r: row 0..3, bb: batch 0..3)
        #pragma unroll
        for (int j = 0; j < 16; j++) acc[j] = 0.f;

        const float* Wp = WV + (size_t)w0 * KVc + lane * 4;

        #pragma unroll 2
        for (int it = 0; it < 12; it++) {
            int cb = it * 128;
            float4 w0v = *(const float4*)(Wp + cb);
            float4 w1v = *(const float4*)(Wp + KVc + cb);
            float4 w2v = *(const float4*)(Wp + 2 * KVc + cb);
            float4 w3v = *(const float4*)(Wp + 3 * KVc + cb);
            int xb = cb + lane * 4;
            #pragma unroll
            for (int bb = 0; bb < 4; bb++) {
                float4 xv = *(const float4*)(xs + (gb0 + bb) * KVc + xb);
                acc[0 * 4 + bb] = fmaf(w0v.x, xv.x, acc[0 * 4 + bb]);
                acc[0 * 4 + bb] = fmaf(w0v.y, xv.y, acc[0 * 4 + bb]);
                acc[0 * 4 + bb] = fmaf(w0v.z, xv.z, acc[0 * 4 + bb]);
                acc[0 * 4 + bb] = fmaf(w0v.w, xv.w, acc[0 * 4 + bb]);
                acc[1 * 4 + bb] = fmaf(w1v.x, xv.x, acc[1 * 4 + bb]);
                acc[1 * 4 + bb] = fmaf(w1v.y, xv.y, acc[1 * 4 + bb]);
                acc[1 * 4 + bb] = fmaf(w1v.z, xv.z, acc[1 * 4 + bb]);
                acc[1 * 4 + bb] = fmaf(w1v.w, xv.w, acc[1 * 4 + bb]);
                acc[2 * 4 + bb] = fmaf(w2v.x, xv.x, acc[2 * 4 + bb]);
                acc[2 * 4 + bb] = fmaf(w2v.y, xv.y, acc[2 * 4 + bb]);
                acc[2 * 4 + bb] = fmaf(w2v.z, xv.z, acc[2 * 4 + bb]);
                acc[2 * 4 + bb] = fmaf(w2v.w, xv.w, acc[2 * 4 + bb]);
                acc[3 * 4 + bb] = fmaf(w3v.x, xv.x, acc[3 * 4 + bb]);
                acc[3 * 4 + bb] = fmaf(w3v.y, xv.y, acc[3 * 4 + bb]);
                acc[3 * 4 + bb] = fmaf(w3v.z, xv.z, acc[3 * 4 + bb]);
                acc[3 * 4 + bb] = fmaf(w3v.w, xv.w, acc[3 * 4 + bb]);
            }
        }

        // fold lanes 16..31 into 0..15, then 4-stage butterfly over 16 accs;
        // lane l (<16) ends with the full sum of acc[l]
        #pragma unroll
        for (int j = 0; j < 16; j++) acc[j] += __shfl_xor_sync(0xffffffffu, acc[j], 16);
        #pragma unroll
        for (int h = 8; h >= 1; h >>= 1) {
            #pragma unroll
            for (int j = 0; j < h; j++) {
                float lo = acc[j];
                float hi = acc[j + h];
                float mine = (lane & h) ? hi : lo;
                float send = (lane & h) ? lo : hi;
                float recv = __shfl_xor_sync(0xffffffffu, send, h);
                acc[j] = mine + recv;
            }
        }

        if (lane < 16) {
            int w = w0 + (lane >> 2);
            int b = gb0 + (lane & 3);
            float ev = acc[0] + __ldg(bV + w);
            int cnt = g_cnt[b * Vc + w];
            float en = (cnt == 0) ? ev : (float)cnt * g_ekval[b * Vc + w];
            en = tanhf(en);
            float p = __expf(en);
            out[b * Vc + w] = p;
            lsum += p;
        }
    }

    // combine lanes sharing a batch: {l, l^4, l^8, l^12} (row bits 2..3);
    // lanes >=16 hold zero and stay in the upper half under these xors.
    lsum += __shfl_xor_sync(0xffffffffu, lsum, 4);
    lsum += __shfl_xor_sync(0xffffffffu, lsum, 8);
    if (lane < 4) sm_ps[warp * 4 + lane] = lsum;
    __syncthreads();

    // block-level deterministic combine: warps of matching group -> batch sums
    if (tid < 8) {
        int b = tid;
        int g = b >> 2;
        int bb = b & 3;
        float s = 0.f;
        #pragma unroll
        for (int wv = 0; wv < 8; wv++)
            if (((jbase + wv) & 1) == g) s += sm_ps[wv * 4 + bb];
        g_psum[blockIdx.x * 8 + b] = s;
    }
}

// ---------------------------------------------------------------------------
// Kernel 3: fused reduce + normalize + g_cnt cleanup.
// grid (125, 8), 256 threads. Each block redundantly (deterministically)
// reduces the 592 per-block partials for its batch (L2-resident), then
// normalizes its 256-element slice. Blocks at x==0 re-zero the g_cnt entries
// touched by this run, restoring the all-zero invariant for the next replay.
// ---------------------------------------------------------------------------
__global__ void norm_kernel(float* __restrict__ out, const int* __restrict__ topics) {
    int b = blockIdx.y;
    int tid = threadIdx.x;
    __shared__ float ssum[8];
    __shared__ float srinv;

    float s = 0.f;
    for (int i = tid; i < GRID_MAIN; i += 256)
        s += g_psum[i * 8 + b];
    #pragma unroll
    for (int h = 16; h >= 1; h >>= 1) s += __shfl_xor_sync(0xffffffffu, s, h);
    if ((tid & 31) == 0) ssum[tid >> 5] = s;
    __syncthreads();
    if (tid == 0) {
        float t = 0.f;
        #pragma unroll
        for (int w = 0; w < 8; w++) t += ssum[w];
        srinv = 1.0f / t;
    }
    __syncthreads();

    // cleanup: restore g_cnt to all-zero (indices touched this run only)
    if (blockIdx.x == 0) {
        for (int t = tid; t < Tc; t += 256)
            g_cnt[b * Vc + topics[b * Tc + t]] = 0;
    }

    int i = blockIdx.x * 256 + tid;   // 125*256 == 32000 exactly
    out[b * Vc + i] *= srinv;
}

// ---------------------------------------------------------------------------
// Launch (3 kernels)
// Input order: output, input_step, context, topic_indexs, [topic_length],
//              W_V, b_V, W_K, b_K
// ---------------------------------------------------------------------------
extern "C" void kernel_launch(void* const* d_in, const int* in_sizes, int n_in,
                              void* d_out, int out_size) {
    const float* outp   = (const float*)d_in[0];
    const float* inp    = (const float*)d_in[1];
    const float* ctx    = (const float*)d_in[2];
    const int*   topics = (const int*)d_in[3];

    int base = 4;
    if (n_in >= 9 && in_sizes[4] <= 4) base = 5;   // skip topic_length scalar

    const float* WV = (const float*)d_in[base + 0];
    const float* bV = (const float*)d_in[base + 1];
    const float* WK = (const float*)d_in[base + 2];
    const float* bK = (const float*)d_in[base + 3];
    float* out = (float*)d_out;

    count_ek_kernel<<<(Bc * Tc) / 2, 256>>>(topics, outp, inp, ctx, WK, bK);
    main_kernel<<<GRID_MAIN, 256>>>(outp, inp, WV, bV, out);
    norm_kernel<<<dim3(Vc / 256, Bc), 256>>>(out, topics);
}

// round 12
// speedup vs baseline: 1.1303x; 1.1303x over previous
#include <cuda_runtime.h>
#include <cstdint>

// Problem constants (fixed shapes for this problem)
#define Bc 8
#define Hc 1024
#define Ec 512
#define Vc 32000
#define Tc 100
#define KVc 1536   // H + E   (x_v width)
#define KKc 2560   // 2H + E  (x_k width)

#define GRID_MAIN 296          // 2 blocks per SM on 148 SMs, single wave
// 8000 tiles = 296*27 + 8 -> first 8 blocks take 28 tiles, rest 27

// Scratch (device globals; no runtime allocation allowed)
__device__ float g_ekval[Bc * Vc];             // e_k values (valid where topic word present)
__device__ float g_psum[GRID_MAIN * Bc];       // per-BLOCK partial softmax sums (ungated)
__device__ float g_rinv[Bc];                   // reciprocal corrected row sums

// ---------------------------------------------------------------------------
// Kernel A (side stream): e_k for each (b, topic word) pair.
// 4 warps per pair (each covers 640 of 2560 cols), smem combine. 800 pairs ->
// 400 blocks x 256 threads. No counts needed (fix recomputes them from smem).
// Runs CONCURRENTLY with main (independent outputs).
// ---------------------------------------------------------------------------
__global__ void __launch_bounds__(256) ek_kernel(const int*   __restrict__ topics,
                                                 const float* __restrict__ outp,
                                                 const float* __restrict__ inp,
                                                 const float* __restrict__ ctx,
                                                 const float* __restrict__ WK,
                                                 const float* __restrict__ bK) {
    __shared__ float part[2][4];

    int tid  = threadIdx.x;
    int warp = tid >> 5;
    int lane = tid & 31;
    int lp   = warp >> 2;        // local pair 0/1
    int q    = warp & 3;         // quarter of the 2560-dot
    int pair = blockIdx.x * 2 + lp;

    int b   = pair / Tc;
    int idx = topics[pair];

    float s = 0.f;
    if (idx != 0) {
        const float* wrow = WK + (size_t)idx * KKc + q * 640;
        int cbase = q * 640 + lane * 4;
        #pragma unroll
        for (int i = 0; i < 5; i++) {
            int cc = cbase + i * 128;
            float4 wv = *(const float4*)(wrow + lane * 4 + i * 128);
            float4 xv;
            if (cc < Hc)            xv = *(const float4*)(outp + b * Hc + cc);
            else if (cc < Hc + Ec)  xv = *(const float4*)(inp  + b * Ec + (cc - Hc));
            else                    xv = *(const float4*)(ctx  + b * Hc + (cc - Hc - Ec));
            s += wv.x * xv.x + wv.y * xv.y + wv.z * xv.z + wv.w * xv.w;
        }
        #pragma unroll
        for (int h = 16; h >= 1; h >>= 1) s += __shfl_xor_sync(0xffffffffu, s, h);
    }
    if (lane == 0) part[lp][q] = s;
    __syncthreads();

    if (tid < 2) {
        int p2 = blockIdx.x * 2 + tid;
        int b2 = p2 / Tc;
        int i2 = topics[p2];
        if (i2 != 0) {
            float e = part[tid][0] + part[tid][1] + part[tid][2] + part[tid][3];
            g_ekval[b2 * Vc + i2] = e + bK[i2];   // duplicates write identical values
        }
    }
}

// ---------------------------------------------------------------------------
// Kernel B (main stream): ungated GEMV + tanh + exp + block partial sums.
// Proven R5 core (4 rows x 8 batches, 48 KB smem, double-buffered W loads),
// gate-free epilogue. Register cap 112 (via launch_bounds 288x2) leaves 8K
// registers per SM free so ek_kernel blocks can co-schedule.
// ---------------------------------------------------------------------------
__global__ void __launch_bounds__(288, 2) main_kernel(const float* __restrict__ outp,
                                                      const float* __restrict__ inp,
                                                      const float* __restrict__ WV,
                                                      const float* __restrict__ bV,
                                                      float* __restrict__ out) {
    __shared__ float xs[Bc * KVc];   // 49152 bytes (exactly 48 KB)
    __shared__ float sm_ps[8 * Bc];  // per-warp batch sums

    int tid  = threadIdx.x;
    int warp = tid >> 5;
    int lane = tid & 31;

    // cooperative fill of x_v = concat(output, input_step) per batch
    for (int i = tid; i < (Bc * KVc) / 4; i += 256) {
        int fi = i * 4;
        int b = fi / KVc;
        int c = fi % KVc;
        float4 v;
        if (c < Hc) v = *(const float4*)(outp + b * Hc + c);
        else        v = *(const float4*)(inp  + b * Ec + (c - Hc));
        *(float4*)(xs + fi) = v;
    }
    __syncthreads();

    int b = lane & 7;
    int r = lane >> 3;
    float lsum = 0.f;

    int blk   = blockIdx.x;
    int tbase = blk * 27 + (blk < 8 ? blk : 8);
    int tcnt  = 27 + (blk < 8 ? 1 : 0);

    #pragma unroll 1
    for (int k = warp; k < tcnt; k += 8) {
        int tile = tbase + k;
        int w0 = tile * 4;
        float acc[32];
        #pragma unroll
        for (int j = 0; j < 32; j++) acc[j] = 0.f;

        const float* Wp = WV + (size_t)w0 * KVc + lane * 4;

        // double-buffered W loads
        float4 wc0 = *(const float4*)(Wp);
        float4 wc1 = *(const float4*)(Wp + KVc);
        float4 wc2 = *(const float4*)(Wp + 2 * KVc);
        float4 wc3 = *(const float4*)(Wp + 3 * KVc);

        #pragma unroll 2
        for (int it = 0; it < 12; it++) {
            float4 wn0, wn1, wn2, wn3;
            if (it < 11) {
                const float* Pn = Wp + (it + 1) * 128;
                wn0 = *(const float4*)(Pn);
                wn1 = *(const float4*)(Pn + KVc);
                wn2 = *(const float4*)(Pn + 2 * KVc);
                wn3 = *(const float4*)(Pn + 3 * KVc);
            }
            int xb = it * 128 + lane * 4;
            #pragma unroll
            for (int bb = 0; bb < 8; bb++) {
                float4 xv = *(const float4*)(xs + bb * KVc + xb);
                acc[0 * 8 + bb] = fmaf(wc0.x, xv.x, acc[0 * 8 + bb]);
                acc[0 * 8 + bb] = fmaf(wc0.y, xv.y, acc[0 * 8 + bb]);
                acc[0 * 8 + bb] = fmaf(wc0.z, xv.z, acc[0 * 8 + bb]);
                acc[0 * 8 + bb] = fmaf(wc0.w, xv.w, acc[0 * 8 + bb]);
                acc[1 * 8 + bb] = fmaf(wc1.x, xv.x, acc[1 * 8 + bb]);
                acc[1 * 8 + bb] = fmaf(wc1.y, xv.y, acc[1 * 8 + bb]);
                acc[1 * 8 + bb] = fmaf(wc1.z, xv.z, acc[1 * 8 + bb]);
                acc[1 * 8 + bb] = fmaf(wc1.w, xv.w, acc[1 * 8 + bb]);
                acc[2 * 8 + bb] = fmaf(wc2.x, xv.x, acc[2 * 8 + bb]);
                acc[2 * 8 + bb] = fmaf(wc2.y, xv.y, acc[2 * 8 + bb]);
                acc[2 * 8 + bb] = fmaf(wc2.z, xv.z, acc[2 * 8 + bb]);
                acc[2 * 8 + bb] = fmaf(wc2.w, xv.w, acc[2 * 8 + bb]);
                acc[3 * 8 + bb] = fmaf(wc3.x, xv.x, acc[3 * 8 + bb]);
                acc[3 * 8 + bb] = fmaf(wc3.y, xv.y, acc[3 * 8 + bb]);
                acc[3 * 8 + bb] = fmaf(wc3.z, xv.z, acc[3 * 8 + bb]);
                acc[3 * 8 + bb] = fmaf(wc3.w, xv.w, acc[3 * 8 + bb]);
            }
            wc0 = wn0; wc1 = wn1; wc2 = wn2; wc3 = wn3;
        }

        // butterfly transpose-reduce: 31 shuffles; lane l ends with sum of acc[l]
        #pragma unroll
        for (int h = 16; h >= 1; h >>= 1) {
            #pragma unroll
            for (int j = 0; j < h; j++) {
                float lo = acc[j];
                float hi = acc[j + h];
                float mine = (lane & h) ? hi : lo;
                float send = (lane & h) ? lo : hi;
                float recv = __shfl_xor_sync(0xffffffffu, send, h);
                acc[j] = mine + recv;
            }
        }

        int w = w0 + r;
        float en = tanhf(acc[0] + __ldg(bV + w));
        float p = __expf(en);
        out[b * Vc + w] = p;
        lsum += p;
    }

    // lanes {l, l^8, l^16, l^24} share batch b = l&7 -> combine, lane<8 writes
    lsum += __shfl_xor_sync(0xffffffffu, lsum, 8);
    lsum += __shfl_xor_sync(0xffffffffu, lsum, 16);
    if (lane < 8) sm_ps[warp * 8 + b] = lsum;
    __syncthreads();

    // block-level deterministic combine: 8 warps -> one value per batch
    if (tid < 8) {
        float s = 0.f;
        #pragma unroll
        for (int wv = 0; wv < 8; wv++) s += sm_ps[wv * 8 + tid];
        g_psum[blockIdx.x * 8 + tid] = s;
    }
}

// ---------------------------------------------------------------------------
// Kernel C: fix-up (after join). One block per batch (grid 8, 256 threads).
// Recomputes counts from topics in smem, patches the <=100 gated words per
// batch, and produces g_rinv (deterministic fixed-order sums).
// ---------------------------------------------------------------------------
__global__ void __launch_bounds__(256) fix_kernel(const int* __restrict__ topics,
                                                  float* __restrict__ out) {
    int b   = blockIdx.x;
    int tid = threadIdx.x;
    __shared__ int   tw[Tc];
    __shared__ float sd[128];
    __shared__ float ssum[8];

    if (tid < Tc) tw[tid] = topics[b * Tc + tid];
    if (tid < 128) sd[tid] = 0.f;
    __syncthreads();

    float d = 0.f;
    if (tid < Tc) {
        int w = tw[tid];
        if (w != 0) {
            bool first = true;
            int cnt = 0;
            #pragma unroll 4
            for (int j = 0; j < Tc; j++) {
                if (tw[j] == w) {
                    cnt++;
                    if (j < tid) first = false;
                }
            }
            if (first) {
                float pnew = __expf(tanhf((float)cnt * g_ekval[b * Vc + w]));
                float pold = out[b * Vc + w];
                out[b * Vc + w] = pnew;
                d = pnew - pold;
            }
        }
    }
    if (tid < 128) sd[tid] = d;

    // psum reduce (296 values, fixed order)
    float s = 0.f;
    if (tid < GRID_MAIN)       s += g_psum[tid * 8 + b];
    if (tid + 256 < GRID_MAIN) s += g_psum[(tid + 256) * 8 + b];
    #pragma unroll
    for (int h = 16; h >= 1; h >>= 1) s += __shfl_xor_sync(0xffffffffu, s, h);
    if ((tid & 31) == 0) ssum[tid >> 5] = s;
    __syncthreads();

    if (tid == 0) {
        float S = 0.f;
        #pragma unroll
        for (int w = 0; w < 8; w++) S += ssum[w];
        float D = 0.f;
        #pragma unroll 8
        for (int j = 0; j < 128; j++) D += sd[j];
        g_rinv[b] = 1.0f / (S + D);
    }
}

// ---------------------------------------------------------------------------
// Kernel D: normalize — pure float4 scale stream (4 MB).
// ---------------------------------------------------------------------------
__global__ void norm_kernel(float* __restrict__ out) {
    int g = blockIdx.x * 256 + threadIdx.x;   // 0..63999 float4
    int b = g / 8000;                         // 8000 float4 per batch row
    float r = g_rinv[b];
    float4 v = ((float4*)out)[g];
    v.x *= r; v.y *= r; v.z *= r; v.w *= r;
    ((float4*)out)[g] = v;
}

// ---------------------------------------------------------------------------
// Launch: fork {ek_kernel || main_kernel} -> join -> fix -> norm.
// Stream/event objects are host-side only (no device memory); created per
// call and intentionally not destroyed (kernel_launch runs O(1) times; a
// forked capture stream must outlive the capture).
// ---------------------------------------------------------------------------
extern "C" void kernel_launch(void* const* d_in, const int* in_sizes, int n_in,
                              void* d_out, int out_size) {
    const float* outp   = (const float*)d_in[0];
    const float* inp    = (const float*)d_in[1];
    const float* ctx    = (const float*)d_in[2];
    const int*   topics = (const int*)d_in[3];

    int base = 4;
    if (n_in >= 9 && in_sizes[4] <= 4) base = 5;   // skip topic_length scalar

    const float* WV = (const float*)d_in[base + 0];
    const float* bV = (const float*)d_in[base + 1];
    const float* WK = (const float*)d_in[base + 2];
    const float* bK = (const float*)d_in[base + 3];
    float* out = (float*)d_out;

    cudaStream_t s2;
    cudaEvent_t e1, e2;
    cudaStreamCreateWithFlags(&s2, cudaStreamNonBlocking);
    cudaEventCreateWithFlags(&e1, cudaEventDisableTiming);
    cudaEventCreateWithFlags(&e2, cudaEventDisableTiming);

    // fork side stream off the main (default) stream
    cudaEventRecord(e1, 0);
    cudaStreamWaitEvent(s2, e1, 0);

    ek_kernel<<<(Bc * Tc) / 2, 256, 0, s2>>>(topics, outp, inp, ctx, WK, bK);
    cudaEventRecord(e2, s2);

    main_kernel<<<GRID_MAIN, 256>>>(outp, inp, WV, bV, out);

    // join: fix needs both main's out/psum and ek's g_ekval
    cudaStreamWaitEvent(0, e2, 0);
    fix_kernel<<<Bc, 256>>>(topics, out);
    norm_kernel<<<250, 256>>>(out);
}

// round 13
// speedup vs baseline: 1.1376x; 1.0064x over previous
#include <cuda_runtime.h>
#include <cstdint>

// Problem constants (fixed shapes for this problem)
#define Bc 8
#define Hc 1024
#define Ec 512
#define Vc 32000
#define Tc 100
#define KVc 1536   // H + E   (x_v width)
#define KKc 2560   // 2H + E  (x_k width)

#define GRID_MAIN 296          // 2 blocks per SM on 148 SMs, single wave
// 8000 tiles = 296*27 + 8 -> first 8 blocks take 28 tiles, rest 27

// Scratch (device globals; no runtime allocation allowed)
__device__ float g_ekval[Bc * Vc];             // e_k values (valid where topic word present)
__device__ float g_psum[GRID_MAIN * Bc];       // per-BLOCK partial softmax sums (ungated)
__device__ float g_rinv[Bc];                   // reciprocal corrected row sums

// ---------------------------------------------------------------------------
// Kernel A (side stream): e_k for each (b, topic word) pair.
// 4 warps per pair (each covers 640 of 2560 cols), smem combine. 800 pairs ->
// 400 blocks x 256 threads. No counts needed (fix recomputes them from smem).
// Runs CONCURRENTLY with main (independent outputs).
// ---------------------------------------------------------------------------
__global__ void __launch_bounds__(256) ek_kernel(const int*   __restrict__ topics,
                                                 const float* __restrict__ outp,
                                                 const float* __restrict__ inp,
                                                 const float* __restrict__ ctx,
                                                 const float* __restrict__ WK,
                                                 const float* __restrict__ bK) {
    __shared__ float part[2][4];

    int tid  = threadIdx.x;
    int warp = tid >> 5;
    int lane = tid & 31;
    int lp   = warp >> 2;        // local pair 0/1
    int q    = warp & 3;         // quarter of the 2560-dot
    int pair = blockIdx.x * 2 + lp;

    int b   = pair / Tc;
    int idx = topics[pair];

    float s = 0.f;
    if (idx != 0) {
        const float* wrow = WK + (size_t)idx * KKc + q * 640;
        int cbase = q * 640 + lane * 4;
        #pragma unroll
        for (int i = 0; i < 5; i++) {
            int cc = cbase + i * 128;
            float4 wv = *(const float4*)(wrow + lane * 4 + i * 128);
            float4 xv;
            if (cc < Hc)            xv = *(const float4*)(outp + b * Hc + cc);
            else if (cc < Hc + Ec)  xv = *(const float4*)(inp  + b * Ec + (cc - Hc));
            else                    xv = *(const float4*)(ctx  + b * Hc + (cc - Hc - Ec));
            s += wv.x * xv.x + wv.y * xv.y + wv.z * xv.z + wv.w * xv.w;
        }
        #pragma unroll
        for (int h = 16; h >= 1; h >>= 1) s += __shfl_xor_sync(0xffffffffu, s, h);
    }
    if (lane == 0) part[lp][q] = s;
    __syncthreads();

    if (tid < 2) {
        int p2 = blockIdx.x * 2 + tid;
        int b2 = p2 / Tc;
        int i2 = topics[p2];
        if (i2 != 0) {
            float e = part[tid][0] + part[tid][1] + part[tid][2] + part[tid][3];
            g_ekval[b2 * Vc + i2] = e + bK[i2];   // duplicates write identical values
        }
    }
}

// ---------------------------------------------------------------------------
// Kernel B (main stream): ungated GEMV + tanh + exp + block partial sums.
// Proven R5 core (4 rows x 8 batches, 48 KB smem, double-buffered W loads,
// natural 128 regs, 2 blocks/SM), gate-free epilogue.
// ---------------------------------------------------------------------------
__global__ void __launch_bounds__(256, 2) main_kernel(const float* __restrict__ outp,
                                                      const float* __restrict__ inp,
                                                      const float* __restrict__ WV,
                                                      const float* __restrict__ bV,
                                                      float* __restrict__ out) {
    __shared__ float xs[Bc * KVc];   // 49152 bytes (exactly 48 KB)
    __shared__ float sm_ps[8 * Bc];  // per-warp batch sums

    int tid  = threadIdx.x;
    int warp = tid >> 5;
    int lane = tid & 31;

    // cooperative fill of x_v = concat(output, input_step) per batch
    for (int i = tid; i < (Bc * KVc) / 4; i += 256) {
        int fi = i * 4;
        int b = fi / KVc;
        int c = fi % KVc;
        float4 v;
        if (c < Hc) v = *(const float4*)(outp + b * Hc + c);
        else        v = *(const float4*)(inp  + b * Ec + (c - Hc));
        *(float4*)(xs + fi) = v;
    }
    __syncthreads();

    int b = lane & 7;
    int r = lane >> 3;
    float lsum = 0.f;

    int blk   = blockIdx.x;
    int tbase = blk * 27 + (blk < 8 ? blk : 8);
    int tcnt  = 27 + (blk < 8 ? 1 : 0);

    #pragma unroll 1
    for (int k = warp; k < tcnt; k += 8) {
        int tile = tbase + k;
        int w0 = tile * 4;
        float acc[32];
        #pragma unroll
        for (int j = 0; j < 32; j++) acc[j] = 0.f;

        const float* Wp = WV + (size_t)w0 * KVc + lane * 4;

        // double-buffered W loads
        float4 wc0 = *(const float4*)(Wp);
        float4 wc1 = *(const float4*)(Wp + KVc);
        float4 wc2 = *(const float4*)(Wp + 2 * KVc);
        float4 wc3 = *(const float4*)(Wp + 3 * KVc);

        #pragma unroll 2
        for (int it = 0; it < 12; it++) {
            float4 wn0, wn1, wn2, wn3;
            if (it < 11) {
                const float* Pn = Wp + (it + 1) * 128;
                wn0 = *(const float4*)(Pn);
                wn1 = *(const float4*)(Pn + KVc);
                wn2 = *(const float4*)(Pn + 2 * KVc);
                wn3 = *(const float4*)(Pn + 3 * KVc);
            }
            int xb = it * 128 + lane * 4;
            #pragma unroll
            for (int bb = 0; bb < 8; bb++) {
                float4 xv = *(const float4*)(xs + bb * KVc + xb);
                acc[0 * 8 + bb] = fmaf(wc0.x, xv.x, acc[0 * 8 + bb]);
                acc[0 * 8 + bb] = fmaf(wc0.y, xv.y, acc[0 * 8 + bb]);
                acc[0 * 8 + bb] = fmaf(wc0.z, xv.z, acc[0 * 8 + bb]);
                acc[0 * 8 + bb] = fmaf(wc0.w, xv.w, acc[0 * 8 + bb]);
                acc[1 * 8 + bb] = fmaf(wc1.x, xv.x, acc[1 * 8 + bb]);
                acc[1 * 8 + bb] = fmaf(wc1.y, xv.y, acc[1 * 8 + bb]);
                acc[1 * 8 + bb] = fmaf(wc1.z, xv.z, acc[1 * 8 + bb]);
                acc[1 * 8 + bb] = fmaf(wc1.w, xv.w, acc[1 * 8 + bb]);
                acc[2 * 8 + bb] = fmaf(wc2.x, xv.x, acc[2 * 8 + bb]);
                acc[2 * 8 + bb] = fmaf(wc2.y, xv.y, acc[2 * 8 + bb]);
                acc[2 * 8 + bb] = fmaf(wc2.z, xv.z, acc[2 * 8 + bb]);
                acc[2 * 8 + bb] = fmaf(wc2.w, xv.w, acc[2 * 8 + bb]);
                acc[3 * 8 + bb] = fmaf(wc3.x, xv.x, acc[3 * 8 + bb]);
                acc[3 * 8 + bb] = fmaf(wc3.y, xv.y, acc[3 * 8 + bb]);
                acc[3 * 8 + bb] = fmaf(wc3.z, xv.z, acc[3 * 8 + bb]);
                acc[3 * 8 + bb] = fmaf(wc3.w, xv.w, acc[3 * 8 + bb]);
            }
            wc0 = wn0; wc1 = wn1; wc2 = wn2; wc3 = wn3;
        }

        // butterfly transpose-reduce: 31 shuffles; lane l ends with sum of acc[l]
        #pragma unroll
        for (int h = 16; h >= 1; h >>= 1) {
            #pragma unroll
            for (int j = 0; j < h; j++) {
                float lo = acc[j];
                float hi = acc[j + h];
                float mine = (lane & h) ? hi : lo;
                float send = (lane & h) ? lo : hi;
                float recv = __shfl_xor_sync(0xffffffffu, send, h);
                acc[j] = mine + recv;
            }
        }

        int w = w0 + r;
        float en = tanhf(acc[0] + __ldg(bV + w));
        float p = __expf(en);
        out[b * Vc + w] = p;
        lsum += p;
    }

    // lanes {l, l^8, l^16, l^24} share batch b = l&7 -> combine, lane<8 writes
    lsum += __shfl_xor_sync(0xffffffffu, lsum, 8);
    lsum += __shfl_xor_sync(0xffffffffu, lsum, 16);
    if (lane < 8) sm_ps[warp * 8 + b] = lsum;
    __syncthreads();

    // block-level deterministic combine: 8 warps -> one value per batch
    if (tid < 8) {
        float s = 0.f;
        #pragma unroll
        for (int wv = 0; wv < 8; wv++) s += sm_ps[wv * 8 + tid];
        g_psum[blockIdx.x * 8 + tid] = s;
    }
}

// ---------------------------------------------------------------------------
// Kernel C: fix-up (after join). One block per batch (grid 8, 256 threads).
// Recomputes counts from topics in smem, patches the <=100 gated words per
// batch, and produces g_rinv (deterministic fixed-order sums).
// ---------------------------------------------------------------------------
__global__ void __launch_bounds__(256) fix_kernel(const int* __restrict__ topics,
                                                  float* __restrict__ out) {
    int b   = blockIdx.x;
    int tid = threadIdx.x;
    __shared__ int   tw[Tc];
    __shared__ float sd[128];
    __shared__ float ssum[8];

    if (tid < Tc) tw[tid] = topics[b * Tc + tid];
    if (tid < 128) sd[tid] = 0.f;
    __syncthreads();

    float d = 0.f;
    if (tid < Tc) {
        int w = tw[tid];
        if (w != 0) {
            bool first = true;
            int cnt = 0;
            #pragma unroll 4
            for (int j = 0; j < Tc; j++) {
                if (tw[j] == w) {
                    cnt++;
                    if (j < tid) first = false;
                }
            }
            if (first) {
                float pnew = __expf(tanhf((float)cnt * g_ekval[b * Vc + w]));
                float pold = out[b * Vc + w];
                out[b * Vc + w] = pnew;
                d = pnew - pold;
            }
        }
    }
    if (tid < 128) sd[tid] = d;

    // psum reduce (296 values, fixed order)
    float s = 0.f;
    if (tid < GRID_MAIN)       s += g_psum[tid * 8 + b];
    if (tid + 256 < GRID_MAIN) s += g_psum[(tid + 256) * 8 + b];
    #pragma unroll
    for (int h = 16; h >= 1; h >>= 1) s += __shfl_xor_sync(0xffffffffu, s, h);
    if ((tid & 31) == 0) ssum[tid >> 5] = s;
    __syncthreads();

    if (tid == 0) {
        float S = 0.f;
        #pragma unroll
        for (int w = 0; w < 8; w++) S += ssum[w];
        float D = 0.f;
        #pragma unroll 8
        for (int j = 0; j < 128; j++) D += sd[j];
        g_rinv[b] = 1.0f / (S + D);
    }
}

// ---------------------------------------------------------------------------
// Kernel D: normalize — pure float4 scale stream (4 MB).
// ---------------------------------------------------------------------------
__global__ void norm_kernel(float* __restrict__ out) {
    int g = blockIdx.x * 256 + threadIdx.x;   // 0..63999 float4
    int b = g / 8000;                         // 8000 float4 per batch row
    float r = g_rinv[b];
    float4 v = ((float4*)out)[g];
    v.x *= r; v.y *= r; v.z *= r; v.w *= r;
    ((float4*)out)[g] = v;
}

// ---------------------------------------------------------------------------
// Launch: fork {ek_kernel || main_kernel} -> join -> fix -> norm.
// Stream/event objects are host-side only (no device memory); created per
// call and intentionally not destroyed (kernel_launch runs O(1) times; a
// forked capture stream must outlive the capture).
// ---------------------------------------------------------------------------
extern "C" void kernel_launch(void* const* d_in, const int* in_sizes, int n_in,
                              void* d_out, int out_size) {
    const float* outp   = (const float*)d_in[0];
    const float* inp    = (const float*)d_in[1];
    const float* ctx    = (const float*)d_in[2];
    const int*   topics = (const int*)d_in[3];

    int base = 4;
    if (n_in >= 9 && in_sizes[4] <= 4) base = 5;   // skip topic_length scalar

    const float* WV = (const float*)d_in[base + 0];
    const float* bV = (const float*)d_in[base + 1];
    const float* WK = (const float*)d_in[base + 2];
    const float* bK = (const float*)d_in[base + 3];
    float* out = (float*)d_out;

    cudaStream_t s2;
    cudaEvent_t e1, e2;
    cudaStreamCreateWithFlags(&s2, cudaStreamNonBlocking);
    cudaEventCreateWithFlags(&e1, cudaEventDisableTiming);
    cudaEventCreateWithFlags(&e2, cudaEventDisableTiming);

    // fork side stream off the main (default) stream
    cudaEventRecord(e1, 0);
    cudaStreamWaitEvent(s2, e1, 0);

    ek_kernel<<<(Bc * Tc) / 2, 256, 0, s2>>>(topics, outp, inp, ctx, WK, bK);
    cudaEventRecord(e2, s2);

    main_kernel<<<GRID_MAIN, 256>>>(outp, inp, WV, bV, out);

    // join: fix needs both main's out/psum and ek's g_ekval
    cudaStreamWaitEvent(0, e2, 0);
    fix_kernel<<<Bc, 256>>>(topics, out);
    norm_kernel<<<250, 256>>>(out);
}